// round 8
// baseline (speedup 1.0000x reference)
#include <cuda_runtime.h>
#include <cuda_fp16.h>
#include <cstdint>
#include <cstddef>

// ---------------------------------------------------------------------------
// Problem dims
// ---------------------------------------------------------------------------
#define BATCH 4096
#define FEAT  2048

// GEMM tiling: CTA 128x128, 4 warps of 64x64, BK=64, 3-stage pipeline
#define BM 128
#define BN 128
#define BK 64
#define NCHUNK (FEAT / BK)     // 32
#define STG 3

// Shared memory: row = 64 halfs = 128B = 8 x 16B units.
#define ASTG (BM * 128)                // 16384 B per stage
#define BSTG (BN * 128)                // 16384 B per stage
#define SM_A 0
#define SM_B (STG * ASTG)              // 49152
#define SMEM_BYTES (SM_B + STG * BSTG) // 98304

// ---------------------------------------------------------------------------
// Device scratch (allocation-free rule: __device__ globals)
// ---------------------------------------------------------------------------
__device__ __align__(16) __half g_w[4][(size_t)FEAT * FEAT];     // 64 MB fp16 weights
__device__ __align__(16) __half g_act[2][(size_t)BATCH * FEAT];  // 32 MB activations

// ---------------------------------------------------------------------------
// PTX helpers (plain compute_80-level PTX: legal on compute_103)
// ---------------------------------------------------------------------------
__device__ __forceinline__ uint32_t smem_u32(const void* p) {
    uint32_t a;
    asm("{ .reg .u64 t; cvta.to.shared.u64 t, %1; cvt.u32.u64 %0, t; }"
        : "=r"(a) : "l"(p));
    return a;
}

__device__ __forceinline__ void cp_async16(uint32_t dst, const void* src) {
    asm volatile("cp.async.cg.shared.global [%0], [%1], 16;"
                 :: "r"(dst), "l"(src));
}
#define CP_COMMIT() asm volatile("cp.async.commit_group;" ::: "memory")
#define CP_WAIT(n)  asm volatile("cp.async.wait_group %0;" :: "n"(n) : "memory")

__device__ __forceinline__ void ldm_x4(uint32_t* r, uint32_t addr) {
    asm volatile("ldmatrix.sync.aligned.m8n8.x4.shared.b16 {%0,%1,%2,%3}, [%4];"
                 : "=r"(r[0]), "=r"(r[1]), "=r"(r[2]), "=r"(r[3]) : "r"(addr));
}

__device__ __forceinline__ void mma16816(float* c, const uint32_t* a, const uint32_t* b) {
    asm volatile(
        "mma.sync.aligned.m16n8k16.row.col.f32.f16.f16.f32 "
        "{%0,%1,%2,%3}, {%4,%5,%6,%7}, {%8,%9}, {%0,%1,%2,%3};"
        : "+f"(c[0]), "+f"(c[1]), "+f"(c[2]), "+f"(c[3])
        : "r"(a[0]), "r"(a[1]), "r"(a[2]), "r"(a[3]), "r"(b[0]), "r"(b[1]));
}

// Swizzle for 128B rows (8 x 16B units): phys unit = u ^ (row & 7).
__device__ __forceinline__ uint32_t sw_off(int row, int u) {
    return (uint32_t)(row * 128 + ((u ^ (row & 7)) << 4));
}

// ---------------------------------------------------------------------------
// GEMM + bias + relu:  out[M,N] = relu( A[M,K] @ W[N,K]^T + bias[N] ) in fp16
// 128 threads, warp grid 2x2, warp tile 64x64.
// Co-resident CTAs are DE-PHASED: each CTA walks the K chunks starting at a
// bid-dependent offset, so their serial boundary windows never coincide.
// ---------------------------------------------------------------------------
__global__ void __launch_bounds__(128, 2)
gemm_relu_kernel(const __half* __restrict__ A, const __half* __restrict__ W,
                 const float* __restrict__ bias, __half* __restrict__ out)
{
    extern __shared__ char smem[];
    const uint32_t sb = smem_u32(smem);

    const int tid  = threadIdx.x;
    const int lane = tid & 31;
    const int wid  = tid >> 5;
    const int wm   = wid >> 1;          // 0..1   (64-row slab)
    const int wn   = wid & 1;           // 0..1   (64-col slab)
    const int m0   = blockIdx.x * BM;
    const int n0   = blockIdx.y * BN;
    // phase offset: adjacent bids (co-resident CTAs) get opposite half-phase
    const int phase = ((blockIdx.x + blockIdx.y) & 1) << 4;   // 0 or 16

    // -------- precompute ldmatrix base rows / xor keys (stage-relative) -----
    const int grp = lane >> 3;          // 0..3 (matrix index within x4)
    uint32_t pa[4], qa[4];              // A: per m-tile (16 rows each)
    #pragma unroll
    for (int t = 0; t < 4; t++) {
        int row = wm * 64 + t * 16 + (grp & 1) * 8 + (lane & 7);
        pa[t] = (uint32_t)(row * 128);
        qa[t] = (uint32_t)((grp >> 1) ^ (row & 7));
    }
    uint32_t pb[4], qb[4];              // B: per n-tile pair (16 cols each)
    #pragma unroll
    for (int p = 0; p < 4; p++) {
        int row = wn * 64 + p * 16 + (grp >> 1) * 8 + (lane & 7);
        pb[p] = (uint32_t)(row * 128);
        qb[p] = (uint32_t)((grp & 1) ^ (row & 7));
    }

    // -------- per-thread loader addresses (128 thr -> 16 rows x 8 units) ----
    const int lrow = tid >> 3, lu = tid & 7;
    const __half* agp = A + (size_t)(m0 + lrow) * FEAT + lu * 8;
    const __half* bgp = W + (size_t)(n0 + lrow) * FEAT + lu * 8;

    // j = logical chunk index; physical k chunk = (j + phase) & 31
    auto load_A = [&](int j, int s) {
        const int k0 = ((j + phase) & (NCHUNK - 1)) * BK;
        #pragma unroll
        for (int i = 0; i < 8; i++) {
            int row = lrow + i * 16;
            cp_async16(sb + SM_A + s * ASTG + sw_off(row, lu),
                       agp + (size_t)i * 16 * FEAT + k0);
        }
    };
    auto load_B = [&](int j, int s) {
        const int k0 = ((j + phase) & (NCHUNK - 1)) * BK;
        #pragma unroll
        for (int i = 0; i < 8; i++) {
            int row = lrow + i * 16;
            cp_async16(sb + SM_B + s * BSTG + sw_off(row, lu),
                       bgp + (size_t)i * 16 * FEAT + k0);
        }
        CP_COMMIT();
    };

    // fragment double buffers (shared across chunk boundaries)
    uint32_t af[2][4][4], bf[2][8][2];

    auto preload = [&](int buf, uint32_t ab, uint32_t bb, uint32_t ux) {
        #pragma unroll
        for (int t = 0; t < 4; t++)
            ldm_x4(af[buf][t], ab + pa[t] + ((qa[t] ^ ux) << 4));
        #pragma unroll
        for (int p = 0; p < 4; p++) {
            uint32_t r[4];
            ldm_x4(r, bb + pb[p] + ((qb[p] ^ ux) << 4));
            bf[buf][2 * p][0] = r[0]; bf[buf][2 * p][1] = r[1];
            bf[buf][2 * p + 1][0] = r[2]; bf[buf][2 * p + 1][1] = r[3];
        }
    };

    float acc[4][8][4];
    #pragma unroll
    for (int t = 0; t < 4; t++)
        #pragma unroll
        for (int n = 0; n < 8; n++)
            #pragma unroll
            for (int e = 0; e < 4; e++) acc[t][n][e] = 0.0f;

    // prologue: two chunks in flight; chunk 0 kstep 0 fragments preloaded
    load_A(0, 0); load_B(0, 0);
    load_A(1, 1); load_B(1, 1);
    CP_WAIT(1);                 // chunk 0 complete
    __syncthreads();
    preload(0, sb + SM_A, sb + SM_B, 0);

    int s = 0;
    for (int i = 0; i < NCHUNK; i++) {
        const uint32_t ab = sb + SM_A + s * ASTG;
        const uint32_t bb = sb + SM_B + s * BSTG;
        int ls = s + 2; if (ls >= STG) ls -= STG;
        const bool more = (i + 2 < NCHUNK);

        // spread the cp.async burst: A now, B after kstep 0's work
        if (more) load_A(i + 2, ls);

        // ksteps 0..2: preload k+1, MMA k
        #pragma unroll
        for (int ks = 0; ks < 3; ks++) {
            const int cur = ks & 1;
            preload(cur ^ 1, ab, bb, (uint32_t)(2 * (ks + 1)));
            if (ks == 0 && more) load_B(i + 2, ls);
            #pragma unroll
            for (int t = 0; t < 4; t++)
                #pragma unroll
                for (int n = 0; n < 8; n++)
                    mma16816(acc[t][n], af[cur][t], bf[cur][n]);
        }

        // chunk boundary: make chunk i+1 visible, preload its kstep 0 into
        // buf0 (kstep 3 uses buf1), THEN issue kstep-3 MMAs to cover latency.
        if (i + 1 < NCHUNK) {
            CP_WAIT(1);         // chunk i+1 complete (group accounting, STG=3)
            __syncthreads();    // all threads' copies + all reads ordered
            int ns = s + 1; if (ns >= STG) ns -= STG;
            preload(0, sb + SM_A + ns * ASTG, sb + SM_B + ns * BSTG, 0);
        }
        #pragma unroll
        for (int t = 0; t < 4; t++)
            #pragma unroll
            for (int n = 0; n < 8; n++)
                mma16816(acc[t][n], af[1][t], bf[1][n]);

        if (++s == STG) s = 0;
    }

    // -------- epilogue: bias + relu + fp16 store --------
    #pragma unroll
    for (int t = 0; t < 4; t++) {
        const int r0 = m0 + wm * 64 + t * 16 + (lane >> 2);
        #pragma unroll
        for (int n = 0; n < 8; n++) {
            const int col = n0 + wn * 64 + n * 8 + (lane & 3) * 2;
            const float2 bv = *reinterpret_cast<const float2*>(bias + col);
            float f0 = fmaxf(acc[t][n][0] + bv.x, 0.0f);
            float f1 = fmaxf(acc[t][n][1] + bv.y, 0.0f);
            float f2 = fmaxf(acc[t][n][2] + bv.x, 0.0f);
            float f3 = fmaxf(acc[t][n][3] + bv.y, 0.0f);
            *reinterpret_cast<__half2*>(out + (size_t)r0 * FEAT + col) =
                __floats2half2_rn(f0, f1);
            *reinterpret_cast<__half2*>(out + (size_t)(r0 + 8) * FEAT + col) =
                __floats2half2_rn(f2, f3);
        }
    }
}

// ---------------------------------------------------------------------------
// Fused prep: sigmoid(x*s+c)->fp16 activations  AND  fp32->fp16 weight convert
// ---------------------------------------------------------------------------
#define SIG_N4 ((BATCH * FEAT) / 4)          // 2M float4 units
#define CVT_N4 ((FEAT * FEAT) / 4)           // 1M float4 units per layer

__global__ void prep_kernel(const float* __restrict__ x,
                            const float* __restrict__ cw,
                            const float* __restrict__ cb,
                            __half* __restrict__ o,
                            const float* __restrict__ W0, const float* __restrict__ W1,
                            const float* __restrict__ W2, const float* __restrict__ W3)
{
    const int gsz = gridDim.x * blockDim.x;
    int g = blockIdx.x * blockDim.x + threadIdx.x;
    const float s = cw[0] + cw[1] + cw[2] + cw[3];
    const float c = cb[0];
    const float4* x4 = (const float4*)x;
    uint2* o4 = (uint2*)o;
    const int total = SIG_N4 + 4 * CVT_N4;
    for (; g < total; g += gsz) {
        if (g < SIG_N4) {
            float4 v = x4[g];
            float a0 = 1.0f / (1.0f + __expf(-(v.x * s + c)));
            float a1 = 1.0f / (1.0f + __expf(-(v.y * s + c)));
            float a2 = 1.0f / (1.0f + __expf(-(v.z * s + c)));
            float a3 = 1.0f / (1.0f + __expf(-(v.w * s + c)));
            __half2 h0 = __floats2half2_rn(a0, a1);
            __half2 h1 = __floats2half2_rn(a2, a3);
            o4[g] = make_uint2(*reinterpret_cast<uint32_t*>(&h0),
                               *reinterpret_cast<uint32_t*>(&h1));
        } else {
            int i = g - SIG_N4;
            int layer = i >> 20;
            int w = i & (CVT_N4 - 1);
            const float* src = (layer == 0) ? W0 : (layer == 1) ? W1
                             : (layer == 2) ? W2 : W3;
            float4 v = ((const float4*)src)[w];
            __half2 h0 = __floats2half2_rn(v.x, v.y);
            __half2 h1 = __floats2half2_rn(v.z, v.w);
            ((uint2*)g_w[layer])[w] = make_uint2(*reinterpret_cast<uint32_t*>(&h0),
                                                 *reinterpret_cast<uint32_t*>(&h1));
        }
    }
}

// ---------------------------------------------------------------------------
// Head: out[b, j] = sum_k h[b,k] * Wh[j,k] + bh[j], j in {0,1}
// ---------------------------------------------------------------------------
__global__ void head_kernel(const __half* __restrict__ h, const float* __restrict__ Wh,
                            const float* __restrict__ bh, float* __restrict__ out)
{
    const int b = blockIdx.x;
    const int t = threadIdx.x;  // 256 threads, 8 halfs each
    const uint4* hr = (const uint4*)(h + (size_t)b * FEAT);
    uint4 v = hr[t];
    __half2* hp = (__half2*)&v;
    float hv[8];
    #pragma unroll
    for (int e = 0; e < 4; e++) {
        float2 f = __half22float2(hp[e]);
        hv[2 * e] = f.x;
        hv[2 * e + 1] = f.y;
    }
    const float4* w0 = (const float4*)Wh;
    const float4* w1 = (const float4*)(Wh + FEAT);
    float4 a0 = w0[2 * t], a1 = w0[2 * t + 1];
    float4 c0 = w1[2 * t], c1 = w1[2 * t + 1];
    float s0 = hv[0] * a0.x + hv[1] * a0.y + hv[2] * a0.z + hv[3] * a0.w
             + hv[4] * a1.x + hv[5] * a1.y + hv[6] * a1.z + hv[7] * a1.w;
    float s1 = hv[0] * c0.x + hv[1] * c0.y + hv[2] * c0.z + hv[3] * c0.w
             + hv[4] * c1.x + hv[5] * c1.y + hv[6] * c1.z + hv[7] * c1.w;
    #pragma unroll
    for (int off = 16; off; off >>= 1) {
        s0 += __shfl_down_sync(0xFFFFFFFFu, s0, off);
        s1 += __shfl_down_sync(0xFFFFFFFFu, s1, off);
    }
    __shared__ float r0[8], r1[8];
    if ((t & 31) == 0) { r0[t >> 5] = s0; r1[t >> 5] = s1; }
    __syncthreads();
    if (t == 0) {
        float x0 = 0.0f, x1 = 0.0f;
        #pragma unroll
        for (int w = 0; w < 8; w++) { x0 += r0[w]; x1 += r1[w]; }
        out[b * 2 + 0] = x0 + bh[0];
        out[b * 2 + 1] = x1 + bh[1];
    }
}

// ---------------------------------------------------------------------------
// Launch
// ---------------------------------------------------------------------------
extern "C" void kernel_launch(void* const* d_in, const int* in_sizes, int n_in,
                              void* d_out, int out_size)
{
    const float* x  = (const float*)d_in[0];
    const float* cw = (const float*)d_in[1];
    const float* cb = (const float*)d_in[2];
    const float* Ws[4] = {(const float*)d_in[3], (const float*)d_in[5],
                          (const float*)d_in[7], (const float*)d_in[9]};
    const float* bs[4] = {(const float*)d_in[4], (const float*)d_in[6],
                          (const float*)d_in[8], (const float*)d_in[10]};
    const float* Wh = (const float*)d_in[11];
    const float* bh = (const float*)d_in[12];
    float* out = (float*)d_out;

    __half* wbuf = nullptr;
    __half* act  = nullptr;
    cudaGetSymbolAddress((void**)&wbuf, g_w);
    cudaGetSymbolAddress((void**)&act, g_act);
    __half* bufs[2] = {act, act + (size_t)BATCH * FEAT};

    cudaFuncSetAttribute(gemm_relu_kernel,
                         cudaFuncAttributeMaxDynamicSharedMemorySize, SMEM_BYTES);

    prep_kernel<<<2368, 256>>>(x, cw, cb, bufs[0], Ws[0], Ws[1], Ws[2], Ws[3]);

    dim3 grid(BATCH / BM, FEAT / BN);
    for (int l = 0; l < 4; l++) {
        gemm_relu_kernel<<<grid, 128, SMEM_BYTES>>>(
            bufs[l & 1], wbuf + (size_t)l * FEAT * FEAT, bs[l], bufs[(l + 1) & 1]);
    }
    head_kernel<<<BATCH, 256>>>(bufs[0], Wh, bh, out);
}

// round 9
// speedup vs baseline: 1.0763x; 1.0763x over previous
#include <cuda_runtime.h>
#include <cuda_fp16.h>
#include <cstdint>
#include <cstddef>

// ---------------------------------------------------------------------------
// Problem dims
// ---------------------------------------------------------------------------
#define BATCH 4096
#define FEAT  2048

// GEMM tiling: CTA 128x128, 4 warps of 64x64, BK=64, 3-stage pipeline
#define BM 128
#define BN 128
#define BK 64
#define NCHUNK (FEAT / BK)     // 32
#define STG 3

#define GRID_MN ((BATCH / BM) * (FEAT / BN))   // 512 GEMM CTAs
#define CVT_CTAS 64                            // free-rider converter CTAs

// Shared memory: row = 64 halfs = 128B = 8 x 16B units.
#define ASTG (BM * 128)                // 16384 B per stage
#define BSTG (BN * 128)                // 16384 B per stage
#define SM_A 0
#define SM_B (STG * ASTG)              // 49152
#define SMEM_BYTES (SM_B + STG * BSTG) // 98304

// ---------------------------------------------------------------------------
// Device scratch (allocation-free rule: __device__ globals)
// ---------------------------------------------------------------------------
__device__ __align__(16) __half g_w[4][(size_t)FEAT * FEAT];     // 64 MB fp16 weights
__device__ __align__(16) __half g_act[2][(size_t)BATCH * FEAT];  // 32 MB activations

// ---------------------------------------------------------------------------
// PTX helpers (plain compute_80-level PTX: legal on compute_103)
// ---------------------------------------------------------------------------
__device__ __forceinline__ uint32_t smem_u32(const void* p) {
    uint32_t a;
    asm("{ .reg .u64 t; cvta.to.shared.u64 t, %1; cvt.u32.u64 %0, t; }"
        : "=r"(a) : "l"(p));
    return a;
}

__device__ __forceinline__ void cp_async16(uint32_t dst, const void* src) {
    asm volatile("cp.async.cg.shared.global [%0], [%1], 16;"
                 :: "r"(dst), "l"(src));
}
#define CP_COMMIT() asm volatile("cp.async.commit_group;" ::: "memory")
#define CP_WAIT(n)  asm volatile("cp.async.wait_group %0;" :: "n"(n) : "memory")

__device__ __forceinline__ void ldm_x4(uint32_t* r, uint32_t addr) {
    asm volatile("ldmatrix.sync.aligned.m8n8.x4.shared.b16 {%0,%1,%2,%3}, [%4];"
                 : "=r"(r[0]), "=r"(r[1]), "=r"(r[2]), "=r"(r[3]) : "r"(addr));
}

__device__ __forceinline__ void mma16816(float* c, const uint32_t* a, const uint32_t* b) {
    asm volatile(
        "mma.sync.aligned.m16n8k16.row.col.f32.f16.f16.f32 "
        "{%0,%1,%2,%3}, {%4,%5,%6,%7}, {%8,%9}, {%0,%1,%2,%3};"
        : "+f"(c[0]), "+f"(c[1]), "+f"(c[2]), "+f"(c[3])
        : "r"(a[0]), "r"(a[1]), "r"(a[2]), "r"(a[3]), "r"(b[0]), "r"(b[1]));
}

// Swizzle for 128B rows (8 x 16B units): phys unit = u ^ (row & 7).
__device__ __forceinline__ uint32_t sw_off(int row, int u) {
    return (uint32_t)(row * 128 + ((u ^ (row & 7)) << 4));
}

// ---------------------------------------------------------------------------
// GEMM + bias + relu:  out[M,N] = relu( A[M,K] @ W[N,K]^T + bias[N] ) in fp16
// bids [0, GRID_MN): GEMM work (R7 schedule — best measured config).
// bids [GRID_MN, GRID_MN+CVT_CTAS): convert next layer's fp32 weights -> fp16
//   (rides in the tail wave's free SM slots; DRAM is idle during the GEMM).
// ---------------------------------------------------------------------------
__global__ void __launch_bounds__(128, 2)
gemm_relu_kernel(const __half* __restrict__ A, const __half* __restrict__ W,
                 const float* __restrict__ bias, __half* __restrict__ out,
                 const float* __restrict__ Wnext, __half* __restrict__ wnext)
{
    const int tid  = threadIdx.x;

    // ---- free-rider converter CTAs ----
    if (blockIdx.x >= GRID_MN) {
        const int cb = blockIdx.x - GRID_MN;
        const int per = (FEAT * FEAT / 4) / CVT_CTAS;      // 16384 float4 per CTA
        const float4* src = (const float4*)Wnext + (size_t)cb * per;
        uint2* dst = (uint2*)(wnext) + (size_t)cb * per;
        #pragma unroll 4
        for (int i = tid; i < per; i += 128) {
            float4 v = src[i];
            __half2 h0 = __floats2half2_rn(v.x, v.y);
            __half2 h1 = __floats2half2_rn(v.z, v.w);
            dst[i] = make_uint2(*reinterpret_cast<uint32_t*>(&h0),
                                *reinterpret_cast<uint32_t*>(&h1));
        }
        return;
    }

    extern __shared__ char smem[];
    const uint32_t sb = smem_u32(smem);

    const int lane = tid & 31;
    const int wid  = tid >> 5;
    const int wm   = wid >> 1;          // 0..1   (64-row slab)
    const int wn   = wid & 1;           // 0..1   (64-col slab)
    const int bx   = blockIdx.x & ((BATCH / BM) - 1);
    const int by   = blockIdx.x >> 5;   // BATCH/BM == 32
    const int m0   = bx * BM;
    const int n0   = by * BN;

    // -------- precompute ldmatrix base rows / xor keys (stage-relative) -----
    const int grp = lane >> 3;          // 0..3 (matrix index within x4)
    uint32_t pa[4], qa[4];              // A: per m-tile (16 rows each)
    #pragma unroll
    for (int t = 0; t < 4; t++) {
        int row = wm * 64 + t * 16 + (grp & 1) * 8 + (lane & 7);
        pa[t] = (uint32_t)(row * 128);
        qa[t] = (uint32_t)((grp >> 1) ^ (row & 7));
    }
    uint32_t pb[4], qb[4];              // B: per n-tile pair (16 cols each)
    #pragma unroll
    for (int p = 0; p < 4; p++) {
        int row = wn * 64 + p * 16 + (grp >> 1) * 8 + (lane & 7);
        pb[p] = (uint32_t)(row * 128);
        qb[p] = (uint32_t)((grp & 1) ^ (row & 7));
    }

    // -------- per-thread loader addresses (128 thr -> 16 rows x 8 units) ----
    const int lrow = tid >> 3, lu = tid & 7;
    const __half* agp = A + (size_t)(m0 + lrow) * FEAT + lu * 8;
    const __half* bgp = W + (size_t)(n0 + lrow) * FEAT + lu * 8;

    auto load_chunk = [&](int ck, int s) {
        const int k0 = ck * BK;
        #pragma unroll
        for (int i = 0; i < 8; i++) {                 // A: 8 groups of 16 rows
            int row = lrow + i * 16;
            cp_async16(sb + SM_A + s * ASTG + sw_off(row, lu),
                       agp + (size_t)i * 16 * FEAT + k0);
        }
        #pragma unroll
        for (int i = 0; i < 8; i++) {                 // B
            int row = lrow + i * 16;
            cp_async16(sb + SM_B + s * BSTG + sw_off(row, lu),
                       bgp + (size_t)i * 16 * FEAT + k0);
        }
        CP_COMMIT();
    };

    // fragment double buffers (shared across chunk boundaries)
    uint32_t af[2][4][4], bf[2][8][2];

    auto preload = [&](int buf, uint32_t ab, uint32_t bb, uint32_t ux) {
        #pragma unroll
        for (int t = 0; t < 4; t++)
            ldm_x4(af[buf][t], ab + pa[t] + ((qa[t] ^ ux) << 4));
        #pragma unroll
        for (int p = 0; p < 4; p++) {
            uint32_t r[4];
            ldm_x4(r, bb + pb[p] + ((qb[p] ^ ux) << 4));
            bf[buf][2 * p][0] = r[0]; bf[buf][2 * p][1] = r[1];
            bf[buf][2 * p + 1][0] = r[2]; bf[buf][2 * p + 1][1] = r[3];
        }
    };

    float acc[4][8][4];
    #pragma unroll
    for (int t = 0; t < 4; t++)
        #pragma unroll
        for (int n = 0; n < 8; n++)
            #pragma unroll
            for (int e = 0; e < 4; e++) acc[t][n][e] = 0.0f;

    // prologue: two chunks in flight; chunk 0 kstep 0 fragments preloaded
    load_chunk(0, 0);
    load_chunk(1, 1);
    CP_WAIT(1);                 // chunk 0 complete
    __syncthreads();
    preload(0, sb + SM_A, sb + SM_B, 0);

    int s = 0;
    for (int i = 0; i < NCHUNK; i++) {
        const uint32_t ab = sb + SM_A + s * ASTG;
        const uint32_t bb = sb + SM_B + s * BSTG;

        // issue next-next chunk's loads (its stage was fully read during
        // chunk i-1, ordered by the barrier at the end of iteration i-1)
        if (i + 2 < NCHUNK) {
            int ls = s + 2; if (ls >= STG) ls -= STG;
            load_chunk(i + 2, ls);
        }

        // ksteps 0..2: preload k+1, MMA k
        #pragma unroll
        for (int ks = 0; ks < 3; ks++) {
            const int cur = ks & 1;
            preload(cur ^ 1, ab, bb, (uint32_t)(2 * (ks + 1)));
            #pragma unroll
            for (int t = 0; t < 4; t++)
                #pragma unroll
                for (int n = 0; n < 8; n++)
                    mma16816(acc[t][n], af[cur][t], bf[cur][n]);
        }

        // chunk boundary: make chunk i+1 visible, preload its kstep 0 into
        // buf0 (kstep 3 uses buf1), THEN issue kstep-3 MMAs to cover latency.
        if (i + 1 < NCHUNK) {
            CP_WAIT(1);         // chunk i+1 complete (group accounting, STG=3)
            __syncthreads();    // all threads' copies + all reads ordered
            int ns = s + 1; if (ns >= STG) ns -= STG;
            preload(0, sb + SM_A + ns * ASTG, sb + SM_B + ns * BSTG, 0);
        }
        #pragma unroll
        for (int t = 0; t < 4; t++)
            #pragma unroll
            for (int n = 0; n < 8; n++)
                mma16816(acc[t][n], af[1][t], bf[1][n]);

        if (++s == STG) s = 0;
    }

    // -------- epilogue: bias + relu + fp16 store --------
    #pragma unroll
    for (int t = 0; t < 4; t++) {
        const int r0 = m0 + wm * 64 + t * 16 + (lane >> 2);
        #pragma unroll
        for (int n = 0; n < 8; n++) {
            const int col = n0 + wn * 64 + n * 8 + (lane & 3) * 2;
            const float2 bv = *reinterpret_cast<const float2*>(bias + col);
            float f0 = fmaxf(acc[t][n][0] + bv.x, 0.0f);
            float f1 = fmaxf(acc[t][n][1] + bv.y, 0.0f);
            float f2 = fmaxf(acc[t][n][2] + bv.x, 0.0f);
            float f3 = fmaxf(acc[t][n][3] + bv.y, 0.0f);
            *reinterpret_cast<__half2*>(out + (size_t)r0 * FEAT + col) =
                __floats2half2_rn(f0, f1);
            *reinterpret_cast<__half2*>(out + (size_t)(r0 + 8) * FEAT + col) =
                __floats2half2_rn(f2, f3);
        }
    }
}

// ---------------------------------------------------------------------------
// Prep: sigmoid(x*s+c)->fp16 activations AND fp32->fp16 convert of W0 ONLY
// (W1-W3 are converted by free-rider CTAs inside GEMM layers 0-2)
// ---------------------------------------------------------------------------
#define SIG_N4 ((BATCH * FEAT) / 4)          // 2M float4 units
#define CVT_N4 ((FEAT * FEAT) / 4)           // 1M float4 units per layer

__global__ void prep_kernel(const float* __restrict__ x,
                            const float* __restrict__ cw,
                            const float* __restrict__ cb,
                            __half* __restrict__ o,
                            const float* __restrict__ W0)
{
    const int gsz = gridDim.x * blockDim.x;
    int g = blockIdx.x * blockDim.x + threadIdx.x;
    const float s = cw[0] + cw[1] + cw[2] + cw[3];
    const float c = cb[0];
    const float4* x4 = (const float4*)x;
    uint2* o4 = (uint2*)o;
    const int total = SIG_N4 + CVT_N4;
    for (; g < total; g += gsz) {
        if (g < SIG_N4) {
            float4 v = x4[g];
            float a0 = 1.0f / (1.0f + __expf(-(v.x * s + c)));
            float a1 = 1.0f / (1.0f + __expf(-(v.y * s + c)));
            float a2 = 1.0f / (1.0f + __expf(-(v.z * s + c)));
            float a3 = 1.0f / (1.0f + __expf(-(v.w * s + c)));
            __half2 h0 = __floats2half2_rn(a0, a1);
            __half2 h1 = __floats2half2_rn(a2, a3);
            o4[g] = make_uint2(*reinterpret_cast<uint32_t*>(&h0),
                               *reinterpret_cast<uint32_t*>(&h1));
        } else {
            int w = g - SIG_N4;
            float4 v = ((const float4*)W0)[w];
            __half2 h0 = __floats2half2_rn(v.x, v.y);
            __half2 h1 = __floats2half2_rn(v.z, v.w);
            ((uint2*)g_w[0])[w] = make_uint2(*reinterpret_cast<uint32_t*>(&h0),
                                             *reinterpret_cast<uint32_t*>(&h1));
        }
    }
}

// ---------------------------------------------------------------------------
// Head: out[b, j] = sum_k h[b,k] * Wh[j,k] + bh[j], j in {0,1}
// ---------------------------------------------------------------------------
__global__ void head_kernel(const __half* __restrict__ h, const float* __restrict__ Wh,
                            const float* __restrict__ bh, float* __restrict__ out)
{
    const int b = blockIdx.x;
    const int t = threadIdx.x;  // 256 threads, 8 halfs each
    const uint4* hr = (const uint4*)(h + (size_t)b * FEAT);
    uint4 v = hr[t];
    __half2* hp = (__half2*)&v;
    float hv[8];
    #pragma unroll
    for (int e = 0; e < 4; e++) {
        float2 f = __half22float2(hp[e]);
        hv[2 * e] = f.x;
        hv[2 * e + 1] = f.y;
    }
    const float4* w0 = (const float4*)Wh;
    const float4* w1 = (const float4*)(Wh + FEAT);
    float4 a0 = w0[2 * t], a1 = w0[2 * t + 1];
    float4 c0 = w1[2 * t], c1 = w1[2 * t + 1];
    float s0 = hv[0] * a0.x + hv[1] * a0.y + hv[2] * a0.z + hv[3] * a0.w
             + hv[4] * a1.x + hv[5] * a1.y + hv[6] * a1.z + hv[7] * a1.w;
    float s1 = hv[0] * c0.x + hv[1] * c0.y + hv[2] * c0.z + hv[3] * c0.w
             + hv[4] * c1.x + hv[5] * c1.y + hv[6] * c1.z + hv[7] * c1.w;
    #pragma unroll
    for (int off = 16; off; off >>= 1) {
        s0 += __shfl_down_sync(0xFFFFFFFFu, s0, off);
        s1 += __shfl_down_sync(0xFFFFFFFFu, s1, off);
    }
    __shared__ float r0[8], r1[8];
    if ((t & 31) == 0) { r0[t >> 5] = s0; r1[t >> 5] = s1; }
    __syncthreads();
    if (t == 0) {
        float x0 = 0.0f, x1 = 0.0f;
        #pragma unroll
        for (int w = 0; w < 8; w++) { x0 += r0[w]; x1 += r1[w]; }
        out[b * 2 + 0] = x0 + bh[0];
        out[b * 2 + 1] = x1 + bh[1];
    }
}

// ---------------------------------------------------------------------------
// Launch
// ---------------------------------------------------------------------------
extern "C" void kernel_launch(void* const* d_in, const int* in_sizes, int n_in,
                              void* d_out, int out_size)
{
    const float* x  = (const float*)d_in[0];
    const float* cw = (const float*)d_in[1];
    const float* cb = (const float*)d_in[2];
    const float* Ws[4] = {(const float*)d_in[3], (const float*)d_in[5],
                          (const float*)d_in[7], (const float*)d_in[9]};
    const float* bs[4] = {(const float*)d_in[4], (const float*)d_in[6],
                          (const float*)d_in[8], (const float*)d_in[10]};
    const float* Wh = (const float*)d_in[11];
    const float* bh = (const float*)d_in[12];
    float* out = (float*)d_out;

    __half* wbuf = nullptr;
    __half* act  = nullptr;
    cudaGetSymbolAddress((void**)&wbuf, g_w);
    cudaGetSymbolAddress((void**)&act, g_act);
    __half* bufs[2] = {act, act + (size_t)BATCH * FEAT};

    cudaFuncSetAttribute(gemm_relu_kernel,
                         cudaFuncAttributeMaxDynamicSharedMemorySize, SMEM_BYTES);

    prep_kernel<<<1184, 256>>>(x, cw, cb, bufs[0], Ws[0]);

    for (int l = 0; l < 4; l++) {
        const bool cvt = (l < 3);
        const int grid = cvt ? (GRID_MN + CVT_CTAS) : GRID_MN;
        gemm_relu_kernel<<<grid, 128, SMEM_BYTES>>>(
            bufs[l & 1], wbuf + (size_t)l * FEAT * FEAT, bs[l], bufs[(l + 1) & 1],
            cvt ? Ws[l + 1] : nullptr,
            cvt ? (wbuf + (size_t)(l + 1) * FEAT * FEAT) : nullptr);
    }
    head_kernel<<<BATCH, 256>>>(bufs[0], Wh, bh, out);
}